// round 11
// baseline (speedup 1.0000x reference)
#include <cuda_runtime.h>
#include <cuda_fp16.h>
#include <math.h>
#include <stdint.h>

// Problem constants
#define TT 4096   // tokens = B*S
#define EE 64     // experts
#define KK 8      // top_k
#define HH 1024   // hidden
#define FF 512    // expert ffn
#define CC 1024   // capacity

// -------- scratch (__device__ globals; no allocation allowed) --------
__device__ int   g_expert_index[TT * KK];
__device__ float g_weights[TT * KK];
__device__ int   g_pair_pos[TT * KK];
__device__ int   g_row_token[EE * CC];
__device__ int   g_count[EE];
__device__ alignas(16) __half g_xh[(size_t)TT * HH];         // 8 MB  (x in half)
__device__ alignas(16) __half g_hbuf[(size_t)EE * CC * FF];  // 67 MB (half)
__device__ alignas(16) __half g_obuf[(size_t)EE * CC * HH];  // 134 MB (half)

// -------- helpers --------
__device__ __forceinline__ uint32_t smem_to_u32(const void* p) {
    uint32_t a;
    asm("{ .reg .u64 t; cvta.to.shared.u64 t, %1; cvt.u32.u64 %0, t; }"
        : "=r"(a) : "l"(p));
    return a;
}
__device__ __forceinline__ uint2 f4_to_h4(float4 v) {
    __half2 a = __floats2half2_rn(v.x, v.y);
    __half2 b = __floats2half2_rn(v.z, v.w);
    uint2 r;
    r.x = *reinterpret_cast<uint32_t*>(&a);
    r.y = *reinterpret_cast<uint32_t*>(&b);
    return r;
}
__device__ __forceinline__ uint4 f8_to_h8(float4 v0, float4 v1) {
    uint2 a = f4_to_h4(v0);
    uint2 b = f4_to_h4(v1);
    return make_uint4(a.x, a.y, b.x, b.y);
}
__device__ __forceinline__ void ldm_x4(uint32_t* r, uint32_t addr) {
    asm volatile("ldmatrix.sync.aligned.m8n8.x4.shared.b16 {%0,%1,%2,%3}, [%4];"
        : "=r"(r[0]), "=r"(r[1]), "=r"(r[2]), "=r"(r[3]) : "r"(addr));
}
__device__ __forceinline__ void ldm_x4t(uint32_t* r, uint32_t addr) {
    asm volatile("ldmatrix.sync.aligned.m8n8.x4.trans.shared.b16 {%0,%1,%2,%3}, [%4];"
        : "=r"(r[0]), "=r"(r[1]), "=r"(r[2]), "=r"(r[3]) : "r"(addr));
}
__device__ __forceinline__ void mma_f16(float* c, const uint32_t* a, const uint32_t* b) {
    asm volatile(
        "mma.sync.aligned.m16n8k16.row.col.f32.f16.f16.f32 "
        "{%0,%1,%2,%3},{%4,%5,%6,%7},{%8,%9},{%0,%1,%2,%3};"
        : "+f"(c[0]), "+f"(c[1]), "+f"(c[2]), "+f"(c[3])
        : "r"(a[0]), "r"(a[1]), "r"(a[2]), "r"(a[3]), "r"(b[0]), "r"(b[1]));
}
__device__ __forceinline__ void cp_async16(uint32_t dst, const void* src) {
    asm volatile("cp.async.cg.shared.global [%0], [%1], 16;" :: "r"(dst), "l"(src));
}
#define CP_COMMIT() asm volatile("cp.async.commit_group;" ::: "memory")
#define CP_WAIT0()  asm volatile("cp.async.wait_group 0;" ::: "memory")

// ====================================================================
// Kernel 0: x -> half
// ====================================================================
__global__ void cvt_x_kernel(const float* __restrict__ x)
{
    size_t i = ((size_t)blockIdx.x * 256 + threadIdx.x) * 8;
    float4 v0 = *reinterpret_cast<const float4*>(x + i);
    float4 v1 = *reinterpret_cast<const float4*>(x + i + 4);
    *reinterpret_cast<uint4*>(g_xh + i) = f8_to_h8(v0, v1);
}

// ====================================================================
// Kernel 1: router — exact fp32 (must match reference top-k bitwise)
// ====================================================================
__global__ void router_kernel(const float* __restrict__ x,
                              const float* __restrict__ w_router,
                              const float* __restrict__ bias,
                              float* __restrict__ logits_out,
                              float* __restrict__ idx_out)
{
    int t = blockIdx.x;
    __shared__ alignas(16) float sx[HH];
    __shared__ float slog[EE];
    __shared__ float saff[EE];
    __shared__ float ssel[EE];

    const float* xr = x + (size_t)t * HH;
    for (int i = threadIdx.x; i < HH; i += blockDim.x) sx[i] = xr[i];
    __syncthreads();

    int warp = threadIdx.x >> 5;
    int lane = threadIdx.x & 31;

    for (int e = warp * 8; e < warp * 8 + 8; ++e) {
        const float* wr = w_router + (size_t)e * HH;
        float s = 0.f;
        for (int h = lane; h < HH; h += 32) s += sx[h] * wr[h];
        #pragma unroll
        for (int o = 16; o; o >>= 1) s += __shfl_xor_sync(0xffffffffu, s, o);
        if (lane == 0) {
            slog[e] = s;
            if (logits_out) logits_out[(size_t)t * EE + e] = s;
        }
    }
    __syncthreads();

    if (warp == 0) {
        for (int e = lane; e < EE; e += 32) {
            float l = slog[e];
            float a = 1.0f / (1.0f + expf(-l));
            saff[e] = a;
            ssel[e] = a + bias[e];
        }
        __syncwarp();

        int sel_idx[KK];
        #pragma unroll
        for (int k = 0; k < KK; ++k) {
            float v  = ssel[lane];      int id = lane;
            float v2 = ssel[lane + 32];
            if (v2 > v) { v = v2; id = lane + 32; }
            #pragma unroll
            for (int o = 16; o; o >>= 1) {
                float ov = __shfl_xor_sync(0xffffffffu, v, o);
                int   oi = __shfl_xor_sync(0xffffffffu, id, o);
                if (ov > v || (ov == v && oi < id)) { v = ov; id = oi; }
            }
            sel_idx[k] = id;
            if (lane == 0) ssel[id] = -INFINITY;
            __syncwarp();
        }

        if (lane == 0) {
            float wsum = 0.f;
            float wv[KK];
            #pragma unroll
            for (int k = 0; k < KK; ++k) { wv[k] = saff[sel_idx[k]]; wsum += wv[k]; }
            #pragma unroll
            for (int k = 0; k < KK; ++k) {
                g_expert_index[t * KK + k] = sel_idx[k];
                g_weights[t * KK + k]      = wv[k] / wsum;
                if (idx_out) idx_out[(size_t)t * KK + k] = (float)sel_idx[k];
            }
        }
    }
}

// ====================================================================
// Kernel 2: slot assignment (exact order of flattened [t,k])
// ====================================================================
__global__ void pos_kernel()
{
    int e   = blockIdx.x;
    int tid = threadIdx.x;
    const int NP    = TT * KK;
    const int chunk = NP / 256;
    __shared__ int scnt[256];

    int base = tid * chunk;
    int c = 0;
    for (int j = 0; j < chunk; ++j)
        if (g_expert_index[base + j] == e) c++;
    scnt[tid] = c;
    __syncthreads();

    if (tid == 0) {
        int run = 0;
        for (int i = 0; i < 256; ++i) { int v = scnt[i]; scnt[i] = run; run += v; }
        g_count[e] = run;
    }
    __syncthreads();

    int off = scnt[tid];
    for (int j = 0; j < chunk; ++j) {
        int i = base + j;
        if (g_expert_index[i] == e) {
            g_pair_pos[i] = off;
            if (off < CC) g_row_token[e * CC + off] = i / KK;
            off++;
        }
    }
}

// ====================================================================
// Kernel 3: gate+up GEMM + SiLU*u -> hbuf(half)  (mma.sync fp16 k16)
// CTA: M=128, N=64 (gate+up).  BK=64, double-buffered, dynamic SMEM.
// A via cp.async from g_xh; B fp32->half packed at LDG.
// A tile: [128 rows][64 halves], stride 144B.  Bg/Bu: [64 k][64 n], 144B.
// Layout (bytes): A0=0(18432) A1=18432, Bg0=36864(9216) Bg1=46080,
//                 Bu0=55296 Bu1=64512; total 73728.
// grid = (CC/128=8 [m fastest], FF/64=8, EE)
// ====================================================================
__global__ void __launch_bounds__(256, 2) gemm1_mma(const float* __restrict__ w_gate,
                                                    const float* __restrict__ w_up)
{
    const int e  = blockIdx.z;
    const int m0 = blockIdx.x * 128;
    const int n0 = blockIdx.y * 64;

    int cnt = g_count[e];
    cnt = (cnt < CC) ? cnt : CC;
    if (m0 >= cnt) return;

    extern __shared__ unsigned char sbuf[];
    __shared__ int stok[128];

    const int tid  = threadIdx.x;
    const int wid  = tid >> 5;
    const int lane = tid & 31;
    const int wm   = wid >> 1;      // 0..3
    const int wn   = wid & 1;       // 0..1

    if (tid < 128) {
        int slot = m0 + tid;
        if (slot >= cnt) slot = cnt - 1;
        stok[tid] = g_row_token[e * CC + slot];
    }
    __syncthreads();

    const uint32_t sA = smem_to_u32(sbuf);

    // ---- loader constants ----
    // A: row = tid>>1 (0..127), half-offset (tid&1)*32 within 64-halves row
    const __half* a_src = g_xh + (size_t)stok[tid >> 1] * HH + (tid & 1) * 32;
    const uint32_t a_dst_off = (tid >> 1) * 144 + (tid & 1) * 64;
    // B: krow = tid>>2 (0..63), 16 floats at (tid&3)*16
    const float* wg_src = w_gate + (size_t)e * HH * FF + n0 +
                          (size_t)(tid >> 2) * FF + (tid & 3) * 16;
    const float* wu_src = w_up   + (size_t)e * HH * FF + n0 +
                          (size_t)(tid >> 2) * FF + (tid & 3) * 16;
    const uint32_t b_dst_off = (tid >> 2) * 144 + (tid & 3) * 32;

    // ---- fragment address constants ----
    const int fa_row  = lane & 15;
    const int fa_koff = (lane >> 4) * 16;
    const int fb_noff = (wn * 32 + (lane >> 4) * 8) * 2;

    float accg[2][4][4];
    float accu[2][4][4];
    #pragma unroll
    for (int mi = 0; mi < 2; ++mi)
        #pragma unroll
        for (int nj = 0; nj < 4; ++nj)
            #pragma unroll
            for (int qq = 0; qq < 4; ++qq) { accg[mi][nj][qq] = 0.f; accu[mi][nj][qq] = 0.f; }

    // ---- prologue: chunk 0 ----
    {
        #pragma unroll
        for (int c = 0; c < 4; ++c)
            cp_async16(sA + a_dst_off + c * 16, a_src + c * 8);
        CP_COMMIT();
        float4 g0 = *reinterpret_cast<const float4*>(wg_src + 0);
        float4 g1 = *reinterpret_cast<const float4*>(wg_src + 4);
        float4 g2 = *reinterpret_cast<const float4*>(wg_src + 8);
        float4 g3 = *reinterpret_cast<const float4*>(wg_src + 12);
        float4 u0 = *reinterpret_cast<const float4*>(wu_src + 0);
        float4 u1 = *reinterpret_cast<const float4*>(wu_src + 4);
        float4 u2 = *reinterpret_cast<const float4*>(wu_src + 8);
        float4 u3 = *reinterpret_cast<const float4*>(wu_src + 12);
        *reinterpret_cast<uint4*>(sbuf + 36864 + b_dst_off +  0) = f8_to_h8(g0, g1);
        *reinterpret_cast<uint4*>(sbuf + 36864 + b_dst_off + 16) = f8_to_h8(g2, g3);
        *reinterpret_cast<uint4*>(sbuf + 55296 + b_dst_off +  0) = f8_to_h8(u0, u1);
        *reinterpret_cast<uint4*>(sbuf + 55296 + b_dst_off + 16) = f8_to_h8(u2, u3);
    }
    CP_WAIT0();
    __syncthreads();

    const int NK = HH / 64;   // 16
    for (int kc = 0; kc < NK; ++kc) {
        const int cur = kc & 1;
        const bool has_next = (kc + 1 < NK);
        uint4 bgp0, bgp1, bup0, bup1;
        if (has_next) {
            const int k0 = (kc + 1) * 64;
            const uint32_t Ad = sA + (cur ^ 1) * 18432 + a_dst_off;
            #pragma unroll
            for (int c = 0; c < 4; ++c)
                cp_async16(Ad + c * 16, a_src + k0 + c * 8);
            CP_COMMIT();
            const float* gs = wg_src + (size_t)k0 * FF;
            const float* us = wu_src + (size_t)k0 * FF;
            float4 g0 = *reinterpret_cast<const float4*>(gs + 0);
            float4 g1 = *reinterpret_cast<const float4*>(gs + 4);
            bgp0 = f8_to_h8(g0, g1);
            float4 g2 = *reinterpret_cast<const float4*>(gs + 8);
            float4 g3 = *reinterpret_cast<const float4*>(gs + 12);
            bgp1 = f8_to_h8(g2, g3);
            float4 u0 = *reinterpret_cast<const float4*>(us + 0);
            float4 u1 = *reinterpret_cast<const float4*>(us + 4);
            bup0 = f8_to_h8(u0, u1);
            float4 u2 = *reinterpret_cast<const float4*>(us + 8);
            float4 u3 = *reinterpret_cast<const float4*>(us + 12);
            bup1 = f8_to_h8(u2, u3);
        }

        // ---- compute current chunk: 4 ks of k16 ----
        const uint32_t Ab  = sA + cur * 18432;
        const uint32_t Bgb = sA + 36864 + cur * 9216;
        const uint32_t Bub = sA + 55296 + cur * 9216;
        #pragma unroll
        for (int ks = 0; ks < 4; ++ks) {
            uint32_t a[2][4];
            #pragma unroll
            for (int mi = 0; mi < 2; ++mi)
                ldm_x4(a[mi], Ab + (wm * 32 + mi * 16 + fa_row) * 144 + ks * 32 + fa_koff);
            #pragma unroll
            for (int pf = 0; pf < 2; ++pf) {
                uint32_t bg[4], bu[4];
                int boff = (ks * 16 + fa_row) * 144 + fb_noff + pf * 32;
                ldm_x4t(bg, Bgb + boff);
                ldm_x4t(bu, Bub + boff);
                #pragma unroll
                for (int mi = 0; mi < 2; ++mi) {
                    mma_f16(accg[mi][pf * 2 + 0], a[mi], bg + 0);
                    mma_f16(accg[mi][pf * 2 + 1], a[mi], bg + 2);
                    mma_f16(accu[mi][pf * 2 + 0], a[mi], bu + 0);
                    mma_f16(accu[mi][pf * 2 + 1], a[mi], bu + 2);
                }
            }
        }

        if (has_next) {
            unsigned char* nbg = sbuf + 36864 + (cur ^ 1) * 9216 + b_dst_off;
            unsigned char* nbu = sbuf + 55296 + (cur ^ 1) * 9216 + b_dst_off;
            *reinterpret_cast<uint4*>(nbg +  0) = bgp0;
            *reinterpret_cast<uint4*>(nbg + 16) = bgp1;
            *reinterpret_cast<uint4*>(nbu +  0) = bup0;
            *reinterpret_cast<uint4*>(nbu + 16) = bup1;
        }
        CP_WAIT0();
        __syncthreads();
    }

    // ---- epilogue: h = silu(g) * u -> half ----
    const int frow = lane >> 2;
    const int fcol = (lane & 3) * 2;
    #pragma unroll
    for (int mi = 0; mi < 2; ++mi) {
        #pragma unroll
        for (int nj = 0; nj < 4; ++nj) {
            int m = m0 + wm * 32 + mi * 16 + frow;
            int n = n0 + wn * 32 + nj * 8 + fcol;
            #pragma unroll
            for (int half = 0; half < 2; ++half) {
                float g0 = accg[mi][nj][half * 2 + 0];
                float g1 = accg[mi][nj][half * 2 + 1];
                float u0 = accu[mi][nj][half * 2 + 0];
                float u1 = accu[mi][nj][half * 2 + 1];
                float h0 = (g0 / (1.0f + expf(-g0))) * u0;
                float h1 = (g1 / (1.0f + expf(-g1))) * u1;
                *reinterpret_cast<__half2*>(
                    &g_hbuf[((size_t)e * CC + m + half * 8) * FF + n]) =
                    __floats2half2_rn(h0, h1);
            }
        }
    }
}

// ====================================================================
// Kernel 4: down GEMM: hbuf(half) x w_down -> obuf(half)
// CTA: M=128, N=128.  BK=64, double-buffered, dynamic SMEM.
// A tile: [128][64 halves] stride 144B.  B tile: [64 k][128 n] stride 272B.
// Layout: A0=0(18432) A1=18432, B0=36864(17408) B1=54272; total 71680.
// grid = (CC/128=8 [m fastest], HH/128=8, EE)
// ====================================================================
__global__ void __launch_bounds__(256, 2) gemm2_mma(const float* __restrict__ w_down)
{
    const int e  = blockIdx.z;
    const int m0 = blockIdx.x * 128;
    const int n0 = blockIdx.y * 128;

    int cnt = g_count[e];
    cnt = (cnt < CC) ? cnt : CC;
    if (m0 >= cnt) return;

    extern __shared__ unsigned char sbuf[];

    const int tid  = threadIdx.x;
    const int wid  = tid >> 5;
    const int lane = tid & 31;
    const int wm   = wid >> 1;
    const int wn   = wid & 1;

    const uint32_t sA = smem_to_u32(sbuf);

    // A: row = tid>>1, halves offset (tid&1)*32
    const __half* a_src = g_hbuf + ((size_t)e * CC + m0 + (tid >> 1)) * FF + (tid & 1) * 32;
    const uint32_t a_dst_off = (tid >> 1) * 144 + (tid & 1) * 64;
    // B: rows {tid>>3, tid>>3 + 32}, 16 floats at (tid&7)*16
    const float* b_src = w_down + (size_t)e * FF * HH + n0 +
                         (size_t)(tid >> 3) * HH + (tid & 7) * 16;
    const uint32_t b_dst_off = (tid >> 3) * 272 + (tid & 7) * 32;

    const int fa_row  = lane & 15;
    const int fa_koff = (lane >> 4) * 16;
    const int fb_noff = (wn * 64 + (lane >> 4) * 8) * 2;

    float acc[2][8][4];
    #pragma unroll
    for (int mi = 0; mi < 2; ++mi)
        #pragma unroll
        for (int nj = 0; nj < 8; ++nj)
            #pragma unroll
            for (int qq = 0; qq < 4; ++qq) acc[mi][nj][qq] = 0.f;

    // ---- prologue chunk 0 ----
    {
        #pragma unroll
        for (int c = 0; c < 4; ++c)
            cp_async16(sA + a_dst_off + c * 16, a_src + c * 8);
        CP_COMMIT();
        #pragma unroll
        for (int p = 0; p < 2; ++p) {
            const float* bs = b_src + (size_t)p * 32 * HH;
            float4 v0 = *reinterpret_cast<const float4*>(bs + 0);
            float4 v1 = *reinterpret_cast<const float4*>(bs + 4);
            float4 v2 = *reinterpret_cast<const float4*>(bs + 8);
            float4 v3 = *reinterpret_cast<const float4*>(bs + 12);
            unsigned char* d = sbuf + 36864 + b_dst_off + p * 32 * 272;
            *reinterpret_cast<uint4*>(d +  0) = f8_to_h8(v0, v1);
            *reinterpret_cast<uint4*>(d + 16) = f8_to_h8(v2, v3);
        }
    }
    CP_WAIT0();
    __syncthreads();

    const int NK = FF / 64;   // 8
    for (int kc = 0; kc < NK; ++kc) {
        const int cur = kc & 1;
        const bool has_next = (kc + 1 < NK);
        uint4 bp[4];
        if (has_next) {
            const int k0 = (kc + 1) * 64;
            const uint32_t Ad = sA + (cur ^ 1) * 18432 + a_dst_off;
            #pragma unroll
            for (int c = 0; c < 4; ++c)
                cp_async16(Ad + c * 16, a_src + k0 + c * 8);
            CP_COMMIT();
            #pragma unroll
            for (int p = 0; p < 2; ++p) {
                const float* bs = b_src + (size_t)(k0 + p * 32) * HH;
                float4 v0 = *reinterpret_cast<const float4*>(bs + 0);
                float4 v1 = *reinterpret_cast<const float4*>(bs + 4);
                bp[p * 2 + 0] = f8_to_h8(v0, v1);
                float4 v2 = *reinterpret_cast<const float4*>(bs + 8);
                float4 v3 = *reinterpret_cast<const float4*>(bs + 12);
                bp[p * 2 + 1] = f8_to_h8(v2, v3);
            }
        }

        const uint32_t Ab = sA + cur * 18432;
        const uint32_t Bb = sA + 36864 + cur * 17408;
        #pragma unroll
        for (int ks = 0; ks < 4; ++ks) {
            uint32_t a[2][4];
            #pragma unroll
            for (int mi = 0; mi < 2; ++mi)
                ldm_x4(a[mi], Ab + (wm * 32 + mi * 16 + fa_row) * 144 + ks * 32 + fa_koff);
            #pragma unroll
            for (int pf = 0; pf < 4; ++pf) {
                uint32_t b[4];
                ldm_x4t(b, Bb + (ks * 16 + fa_row) * 272 + fb_noff + pf * 32);
                #pragma unroll
                for (int mi = 0; mi < 2; ++mi) {
                    mma_f16(acc[mi][pf * 2 + 0], a[mi], b + 0);
                    mma_f16(acc[mi][pf * 2 + 1], a[mi], b + 2);
                }
            }
        }

        if (has_next) {
            unsigned char* nb = sbuf + 36864 + (cur ^ 1) * 17408 + b_dst_off;
            *reinterpret_cast<uint4*>(nb +  0)            = bp[0];
            *reinterpret_cast<uint4*>(nb + 16)            = bp[1];
            *reinterpret_cast<uint4*>(nb + 32 * 272 +  0) = bp[2];
            *reinterpret_cast<uint4*>(nb + 32 * 272 + 16) = bp[3];
        }
        CP_WAIT0();
        __syncthreads();
    }

    const int frow = lane >> 2;
    const int fcol = (lane & 3) * 2;
    #pragma unroll
    for (int mi = 0; mi < 2; ++mi) {
        #pragma unroll
        for (int nj = 0; nj < 8; ++nj) {
            int m = m0 + wm * 32 + mi * 16 + frow;
            int n = n0 + wn * 64 + nj * 8 + fcol;
            #pragma unroll
            for (int half = 0; half < 2; ++half) {
                *reinterpret_cast<__half2*>(
                    &g_obuf[((size_t)e * CC + m + half * 8) * HH + n]) =
                    __floats2half2_rn(acc[mi][nj][half * 2 + 0],
                                      acc[mi][nj][half * 2 + 1]);
            }
        }
    }
}

// ====================================================================
// Kernel 5: combine — y[t] = sum_k w[t,k] * obuf[row(t,k)]  (obuf half)
// ====================================================================
__global__ void combine_kernel(float* __restrict__ y)
{
    int t = blockIdx.x;
    __shared__ int   srow[KK];
    __shared__ float sw[KK];
    if (threadIdx.x < KK) {
        int i = t * KK + threadIdx.x;
        int e = g_expert_index[i];
        int p = g_pair_pos[i];
        srow[threadIdx.x] = (p < CC) ? (e * CC + p) : -1;
        sw[threadIdx.x]   = g_weights[i];
    }
    __syncthreads();

    const int h0 = threadIdx.x * 4;     // 256 threads x 4 = 1024
    float a0 = 0.f, a1 = 0.f, a2 = 0.f, a3 = 0.f;
    #pragma unroll
    for (int k = 0; k < KK; ++k) {
        int r = srow[k];
        if (r >= 0) {
            float wk = sw[k];
            uint2 v = *reinterpret_cast<const uint2*>(&g_obuf[(size_t)r * HH + h0]);
            __half2 p0 = *reinterpret_cast<__half2*>(&v.x);
            __half2 p1 = *reinterpret_cast<__half2*>(&v.y);
            float2 f0 = __half22float2(p0);
            float2 f1 = __half22float2(p1);
            a0 += wk * f0.x; a1 += wk * f0.y;
            a2 += wk * f1.x; a3 += wk * f1.y;
        }
    }
    *reinterpret_cast<float4*>(&y[(size_t)t * HH + h0]) = make_float4(a0, a1, a2, a3);
}

// ====================================================================
extern "C" void kernel_launch(void* const* d_in, const int* in_sizes, int n_in,
                              void* d_out, int out_size)
{
    const float* x        = (const float*)d_in[0];
    const float* w_router = (const float*)d_in[1];
    const float* bias     = (const float*)d_in[2];
    const float* w_gate   = (const float*)d_in[3];
    const float* w_up     = (const float*)d_in[4];
    const float* w_down   = (const float*)d_in[5];

    float* y = (float*)d_out;
    float* logits_out = nullptr;
    float* idx_out    = nullptr;
    long long base = (long long)TT * HH;
    if ((long long)out_size >= base + (long long)TT * EE)
        logits_out = y + base;
    if ((long long)out_size >= base + (long long)TT * EE + (long long)TT * KK)
        idx_out = y + base + (long long)TT * EE;

    const int SMEM1 = 73728;
    const int SMEM2 = 71680;
    cudaFuncSetAttribute(gemm1_mma, cudaFuncAttributeMaxDynamicSharedMemorySize, SMEM1);
    cudaFuncSetAttribute(gemm2_mma, cudaFuncAttributeMaxDynamicSharedMemorySize, SMEM2);

    cvt_x_kernel<<<(TT * HH) / (256 * 8), 256>>>(x);
    router_kernel<<<TT, 256>>>(x, w_router, bias, logits_out, idx_out);
    pos_kernel<<<EE, 256>>>();
    gemm1_mma<<<dim3(CC / 128, FF / 64, EE), 256, SMEM1>>>(w_gate, w_up);
    gemm2_mma<<<dim3(CC / 128, HH / 128, EE), 256, SMEM2>>>(w_down);
    combine_kernel<<<TT, 256>>>(y);
}